// round 16
// baseline (speedup 1.0000x reference)
#include <cuda_runtime.h>
#include <math.h>

#define NN 10000
#define EE 160000
#define FF 32
#define NCH 9
#define NPAD 12                 // padded channel dim (16B-aligned lane chunks)
#define NODE_F4 (FF * NPAD / 4) // 96 float4 per node

typedef unsigned long long u64t;

// ---------------- device scratch (static, no allocations) ----------------
__device__ float4 g_x4[NN * NODE_F4];    // [node][feature][ch(12)]
__device__ float4 g_y4[NN * NODE_F4];    // message sum (fully overwritten per iter)
__device__ float  g_geo[EE * 25];        // per edge: sph[9], rad[16]
__device__ int    g_cnt[NN];             // histogram / scatter cursor
__device__ int    g_off[NN + 1];         // CSR offsets
__device__ int    g_csr_src[EE];         // src node per CSR slot
__device__ int    g_csr_eid[EE];         // original edge id per CSR slot

// ---------------- packed f32x2 helpers ------------------------------------
__device__ __forceinline__ u64t pk2(float lo, float hi) {
    u64t r; asm("mov.b64 %0, {%1, %2};" : "=l"(r) : "f"(lo), "f"(hi)); return r;
}
__device__ __forceinline__ void upk2(u64t v, float& lo, float& hi) {
    asm("mov.b64 {%0, %1}, %2;" : "=f"(lo), "=f"(hi) : "l"(v));
}
__device__ __forceinline__ u64t fma2_(u64t a, u64t b, u64t c) {
    u64t r; asm("fma.rn.f32x2 %0, %1, %2, %3;" : "=l"(r) : "l"(a), "l"(b), "l"(c)); return r;
}
__device__ __forceinline__ u64t mul2_(u64t a, u64t b) {
    u64t r; asm("mul.rn.f32x2 %0, %1, %2;" : "=l"(r) : "l"(a), "l"(b)); return r;
}

// ---------------- compile-time Gaunt coefficients -------------------------
constexpr double dfc(int n) { double v = 1.0; for (int k = n; k >= 2; k -= 2) v *= (double)k; return v; }
constexpr double sphint(int p, int q, int r) {
    return ((p | q | r) & 1) ? 0.0
         : 12.566370614359172464 * dfc(p - 1) * dfc(q - 1) * dfc(r - 1) / dfc(p + q + r + 1);
}
struct CGTable { float v[9][9][9]; };
constexpr CGTable make_cg() {
    const double TCV[9][2] = {
        {0.28209479177387814, 0.0}, {0.4886025119029199, 0.0}, {0.4886025119029199, 0.0},
        {0.4886025119029199, 0.0}, {1.0925484305920792, 0.0}, {1.0925484305920792, 0.0},
        {3.0 * 0.31539156525252005, -0.31539156525252005}, {1.0925484305920792, 0.0},
        {0.5462742152960396, -0.5462742152960396}};
    const int NTV[9] = {1, 1, 1, 1, 1, 1, 2, 1, 2};
    const int TEV[9][2][3] = {
        {{0,0,0},{0,0,0}}, {{0,1,0},{0,0,0}}, {{0,0,1},{0,0,0}}, {{1,0,0},{0,0,0}},
        {{1,1,0},{0,0,0}}, {{0,1,1},{0,0,0}}, {{0,0,2},{0,0,0}}, {{1,0,1},{0,0,0}},
        {{2,0,0},{0,2,0}}};
    CGTable t{};
    for (int a = 0; a < 9; a++)
      for (int b = 0; b < 9; b++)
        for (int c = 0; c < 9; c++) {
            double g = 0.0;
            for (int i = 0; i < NTV[a]; i++)
              for (int j = 0; j < NTV[b]; j++)
                for (int k = 0; k < NTV[c]; k++)
                    g += TCV[a][i] * TCV[b][j] * TCV[c][k] *
                         sphint(TEV[a][i][0] + TEV[b][j][0] + TEV[c][k][0],
                                TEV[a][i][1] + TEV[b][j][1] + TEV[c][k][1],
                                TEV[a][i][2] + TEV[b][j][2] + TEV[c][k][2]);
            if (g < 1e-6 && g > -1e-6) g = 0.0;
            t.v[a][b][c] = (float)g;
        }
    return t;
}
constexpr CGTable CG_TAB = make_cg();

// ---------------- kernels -------------------------------------------------

__global__ void k_init(const int* __restrict__ z, const float* __restrict__ embed) {
    int idx = blockIdx.x * blockDim.x + threadIdx.x;      // float4 index
    if (idx >= NN * NODE_F4) return;
    if (idx < NN) g_cnt[idx] = 0;
    int r = idx % NODE_F4;
    int n = idx / NODE_F4;
    int f = r / 3, part = r % 3;
    float v0 = (part == 0) ? embed[z[n] * FF + f] : 0.0f;
    g_x4[idx] = make_float4(v0, 0.f, 0.f, 0.f);
}

// geometry + dst histogram (fused)
__global__ void k_geom(const float* __restrict__ pos, const int* __restrict__ dst,
                       const int* __restrict__ src) {
    int e = blockIdx.x * blockDim.x + threadIdx.x;
    if (e >= EE) return;
    int s = src[e], d = dst[e];
    atomicAdd(&g_cnt[d], 1);
    float dx = pos[s * 3 + 0] - pos[d * 3 + 0];
    float dy = pos[s * 3 + 1] - pos[d * 3 + 1];
    float dz = pos[s * 3 + 2] - pos[d * 3 + 2];
    float r = sqrtf(dx * dx + dy * dy + dz * dz + 1e-12f);
    float inv = 1.0f / r;
    float x = dx * inv, y = dy * inv, z = dz * inv;
    const float c0 = 0.28209479177387814f, c1 = 0.4886025119029199f,
                c2a = 1.0925484305920792f, c2b = 0.31539156525252005f,
                c2c = 0.5462742152960396f;
    float* g = &g_geo[(size_t)e * 25];
    g[0] = c0;
    g[1] = c1 * y;  g[2] = c1 * z;  g[3] = c1 * x;
    g[4] = c2a * x * y; g[5] = c2a * y * z;
    g[6] = c2b * (3.0f * z * z - 1.0f);
    g[7] = c2a * x * z; g[8] = c2c * (x * x - y * y);

    float u1 = 1.0f / (1.0f + r);
    float om = 1.0f - u1;
    float A[16], B[16];
    A[0] = 1.0f;
    #pragma unroll
    for (int k = 1; k < 16; k++) A[k] = A[k - 1] * u1;
    B[15] = 1.0f;
    #pragma unroll
    for (int k = 14; k >= 0; k--) B[k] = B[k + 1] * om;
    float t = r * 0.25f;
    float fc = 0.0f;
    if (t < 1.0f) {
        float den = 1.0f - t * t;
        fc = expf(-t * t / den);
    }
    const float binom[16] = {1.f,15.f,105.f,455.f,1365.f,3003.f,5005.f,6435.f,
                             6435.f,5005.f,3003.f,1365.f,455.f,105.f,15.f,1.f};
    #pragma unroll
    for (int k = 0; k < 16; k++) g[9 + k] = binom[k] * A[k] * B[k] * fc;
}

// -------- CSR build: shfl-based scan -> scatter ---------------------------
__global__ void __launch_bounds__(1024) k_scan() {
    __shared__ int wsum[32];
    const int t = threadIdx.x;
    const int lane = t & 31, wid = t >> 5;
    const int chunk = (NN + 1023) / 1024;           // 10
    const int beg = t * chunk;
    const int end = (beg + chunk < NN) ? beg + chunk : NN;
    int sum = 0;
    for (int i = beg; i < end; i++) sum += g_cnt[i];
    int v = sum;
    #pragma unroll
    for (int off = 1; off < 32; off <<= 1) {
        int u = __shfl_up_sync(0xffffffffu, v, off);
        if (lane >= off) v += u;
    }
    if (lane == 31) wsum[wid] = v;
    __syncthreads();
    if (wid == 0) {
        int w = wsum[lane];
        #pragma unroll
        for (int off = 1; off < 32; off <<= 1) {
            int u = __shfl_up_sync(0xffffffffu, w, off);
            if (lane >= off) w += u;
        }
        wsum[lane] = w;
    }
    __syncthreads();
    int base = ((wid > 0) ? wsum[wid - 1] : 0) + (v - sum);   // exclusive prefix
    int run = base;
    for (int i = beg; i < end; i++) {
        int c = g_cnt[i];
        g_off[i] = run;
        run += c;
        g_cnt[i] = 0;                               // reset: reused as cursor
    }
    if (t == 1023) g_off[NN] = EE;
}

__global__ void k_scat(const int* __restrict__ dst, const int* __restrict__ src) {
    int e = blockIdx.x * blockDim.x + threadIdx.x;
    if (e >= EE) return;
    int d = dst[e];
    int slot = g_off[d] + atomicAdd(&g_cnt[d], 1);
    g_csr_src[slot] = src[e];
    g_csr_eid[slot] = e;
}

// edge kernel: warp per dst node, EDGE PAIRS with f32x2-packed tensor product.
__global__ void __launch_bounds__(256, 2)
k_edge(const float* __restrict__ Wb_i) {
    const int lane = threadIdx.x & 31;
    const int warp = (blockIdx.x * blockDim.x + threadIdx.x) >> 5;
    const int nwarp = (gridDim.x * blockDim.x) >> 5;
    const int lsel = (lane < 25 ? lane : 0);

    float w0[16], w1[16], w2[16];
    #pragma unroll
    for (int n = 0; n < 16; n++) {
        w0[n] = Wb_i[(0 * 16 + n) * 32 + lane];
        w1[n] = Wb_i[(1 * 16 + n) * 32 + lane];
        w2[n] = Wb_i[(2 * 16 + n) * 32 + lane];
    }

    const float* gx = (const float*)g_x4;
    float* gy = (float*)g_y4;

    for (int n = warp; n < NN; n += nwarp) {
        const int beg = g_off[n], end = g_off[n + 1];

        float acc[9];
        #pragma unroll
        for (int c = 0; c < 9; c++) acc[c] = 0.f;

        for (int i = beg; i < end; i += 2) {
            const bool has1 = (i + 1 < end);
            // edge 0
            int s0 = g_csr_src[i];
            float gva = g_geo[(size_t)g_csr_eid[i] * 25 + lsel];
            // edge 1 (or dummy: same address, zero geo -> contributes 0)
            int s1 = has1 ? g_csr_src[i + 1] : s0;
            float gvb = has1 ? g_geo[(size_t)g_csr_eid[i + 1] * 25 + lsel] : 0.0f;

            // issue both gathers up front
            const float4* xpa = (const float4*)(gx + (size_t)s0 * (FF * NPAD) + lane * NPAD);
            const float4* xpb = (const float4*)(gx + (size_t)s1 * (FF * NPAD) + lane * NPAD);
            float4 a0 = xpa[0], a1 = xpa[1]; float a8 = ((const float*)xpa)[8];
            float4 b0 = xpb[0], b1 = xpb[1]; float b8 = ((const float*)xpb)[8];

            // R for both edges (scalar, covers gather latency)
            float Ra0 = 0.f, Ra1 = 0.f, Ra2 = 0.f;
            float Rb0 = 0.f, Rb1 = 0.f, Rb2 = 0.f;
            #pragma unroll
            for (int k = 0; k < 16; k++) {
                float rna = __shfl_sync(0xffffffffu, gva, 9 + k);
                float rnb = __shfl_sync(0xffffffffu, gvb, 9 + k);
                Ra0 = fmaf(rna, w0[k], Ra0);
                Ra1 = fmaf(rna, w1[k], Ra1);
                Ra2 = fmaf(rna, w2[k], Ra2);
                Rb0 = fmaf(rnb, w0[k], Rb0);
                Rb1 = fmaf(rnb, w1[k], Rb1);
                Rb2 = fmaf(rnb, w2[k], Rb2);
            }
            u64t R2[3] = { pk2(Ra0, Rb0), pk2(Ra1, Rb1), pk2(Ra2, Rb2) };

            // packed bfv and xa
            u64t bfv2[9];
            #pragma unroll
            for (int b = 0; b < 9; b++) {
                float sa = __shfl_sync(0xffffffffu, gva, b);
                float sb = __shfl_sync(0xffffffffu, gvb, b);
                bfv2[b] = mul2_(pk2(sa, sb), R2[b == 0 ? 0 : (b < 4 ? 1 : 2)]);
            }
            u64t xa2[9] = {
                pk2(a0.x, b0.x), pk2(a0.y, b0.y), pk2(a0.z, b0.z), pk2(a0.w, b0.w),
                pk2(a1.x, b1.x), pk2(a1.y, b1.y), pk2(a1.z, b1.z), pk2(a1.w, b1.w),
                pk2(a8, b8) };

            // diagonal products (packed), accumulate both halves with imm-FFMA
            float pl[9], ph[9];
            #pragma unroll
            for (int a = 0; a < 9; a++) {
                u64t p2 = mul2_(xa2[a], bfv2[a]);
                upk2(p2, pl[a], ph[a]);
            }
#define ACCP(A,C) { constexpr float G_ = CG_TAB.v[A][A][C]; if (G_ != 0.0f) { \
                    acc[C] = fmaf(pl[A], G_, acc[C]); acc[C] = fmaf(ph[A], G_, acc[C]); } }
#define CROSS(A,B) float sl##A##B, sh##A##B; { \
                    u64t s2_ = fma2_(xa2[A], bfv2[B], mul2_(xa2[B], bfv2[A])); \
                    upk2(s2_, sl##A##B, sh##A##B); }
#define ACCS(A,B,C) { constexpr float G_ = CG_TAB.v[A][B][C]; if (G_ != 0.0f) { \
                    acc[C] = fmaf(sl##A##B, G_, acc[C]); acc[C] = fmaf(sh##A##B, G_, acc[C]); } }
            ACCP(0,0) ACCP(0,6) ACCP(0,8)
            ACCP(1,0) ACCP(1,6) ACCP(1,8)
            ACCP(2,0) ACCP(2,6) ACCP(2,8)
            ACCP(3,0) ACCP(3,6) ACCP(3,8)
            ACCP(4,0) ACCP(4,6) ACCP(4,8)
            ACCP(5,0) ACCP(5,6) ACCP(5,8)
            ACCP(6,0) ACCP(6,6) ACCP(6,8)
            ACCP(7,0) ACCP(7,6) ACCP(7,8)
            ACCP(8,0) ACCP(8,6) ACCP(8,8)

            CROSS(0,6) CROSS(0,8) CROSS(6,8)
            ACCS(0,6,0) ACCS(0,6,6) ACCS(0,6,8)
            ACCS(0,8,0) ACCS(0,8,6) ACCS(0,8,8)
            ACCS(6,8,0) ACCS(6,8,6) ACCS(6,8,8)

            CROSS(0,1) CROSS(6,1) CROSS(8,1) CROSS(3,4) CROSS(2,5)
            ACCS(0,1,1) ACCS(6,1,1) ACCS(8,1,1) ACCS(3,4,1) ACCS(2,5,1)

            CROSS(0,2) CROSS(6,2) CROSS(8,2) CROSS(3,7) CROSS(1,5)
            ACCS(0,2,2) ACCS(6,2,2) ACCS(8,2,2) ACCS(3,7,2) ACCS(1,5,2)

            CROSS(0,3) CROSS(6,3) CROSS(8,3) CROSS(1,4) CROSS(2,7)
            ACCS(0,3,3) ACCS(6,3,3) ACCS(8,3,3) ACCS(1,4,3) ACCS(2,7,3)

            CROSS(0,4) CROSS(6,4) CROSS(8,4) CROSS(1,3) CROSS(5,7)
            ACCS(0,4,4) ACCS(6,4,4) ACCS(8,4,4) ACCS(1,3,4) ACCS(5,7,4)

            CROSS(0,5) CROSS(6,5) CROSS(8,5) CROSS(1,2) CROSS(4,7)
            ACCS(0,5,5) ACCS(6,5,5) ACCS(8,5,5) ACCS(1,2,5) ACCS(4,7,5)

            CROSS(0,7) CROSS(6,7) CROSS(8,7) CROSS(2,3) CROSS(4,5)
            ACCS(0,7,7) ACCS(6,7,7) ACCS(8,7,7) ACCS(2,3,7) ACCS(4,5,7)
#undef ACCP
#undef CROSS
#undef ACCS
        }

        float4* yp4 = (float4*)(gy + (size_t)n * (FF * NPAD) + lane * NPAD);
        yp4[0] = make_float4(acc[0], acc[1], acc[2], acc[3]);
        yp4[1] = make_float4(acc[4], acc[5], acc[6], acc[7]);
        yp4[2] = make_float4(acc[8], 0.f, 0.f, 0.f);
    }
}

// node kernel: warp per node, lane = feature, shfl-broadcast matmul.
__global__ void __launch_bounds__(256)
k_node(const float* __restrict__ W1, const float* __restrict__ b1,
       const float* __restrict__ W2, const float* __restrict__ b2) {
    __shared__ float sW1[3 * 32 * 32], sW2[3 * 32 * 32], sb1[32], sb2[32];
    int t = threadIdx.x;
    for (int i = t; i < 3072; i += 256) { sW1[i] = W1[i]; sW2[i] = W2[i]; }
    if (t < 32) { sb1[t] = b1[t]; sb2[t] = b2[t]; }
    __syncthreads();

    int lane = t & 31;
    int n = (blockIdx.x * 256 + t) >> 5;
    if (n >= NN) return;

    const int base4 = n * NODE_F4 + lane * 3;
    float4 xA = g_x4[base4 + 0], xB = g_x4[base4 + 1], xC = g_x4[base4 + 2];
    float4 yA = g_y4[base4 + 0], yB = g_y4[base4 + 1], yC = g_y4[base4 + 2];

    const int DEGc[9] = {0, 1, 1, 1, 2, 2, 2, 2, 2};
    float yv[9], h[9], o[9];
    yv[0] = xA.x + yA.x; yv[1] = xA.y + yA.y; yv[2] = xA.z + yA.z; yv[3] = xA.w + yA.w;
    yv[4] = xB.x + yB.x; yv[5] = xB.y + yB.y; yv[6] = xB.z + yB.z; yv[7] = xB.w + yB.w;
    yv[8] = xC.x + yC.x;

    #pragma unroll
    for (int c = 0; c < 9; c++) {
        int d = DEGc[c];
        float acc = (c == 0) ? sb1[lane] : 0.0f;
        #pragma unroll
        for (int f = 0; f < 32; f++) {
            float v = __shfl_sync(0xffffffffu, yv[c], f);
            acc = fmaf(v, sW1[(d * 32 + f) * 32 + lane], acc);
        }
        h[c] = acc / (1.0f + __expf(-acc));   // silu
    }
    #pragma unroll
    for (int c = 0; c < 9; c++) {
        int d = DEGc[c];
        float acc = (c == 0) ? sb2[lane] : 0.0f;
        #pragma unroll
        for (int f = 0; f < 32; f++) {
            float v = __shfl_sync(0xffffffffu, h[c], f);
            acc = fmaf(v, sW2[(d * 32 + f) * 32 + lane], acc);
        }
        o[c] = acc;
    }
    g_x4[base4 + 0] = make_float4(xA.x + o[0], xA.y + o[1], xA.z + o[2], xA.w + o[3]);
    g_x4[base4 + 1] = make_float4(xB.x + o[4], xB.y + o[5], xB.z + o[6], xB.w + o[7]);
    g_x4[base4 + 2] = make_float4(xC.x + o[8], 0.f, 0.f, 0.f);
}

// output head: mono (N,4) then dip (N,3,4)
__global__ void __launch_bounds__(256)
k_out(const int* __restrict__ z, const float* __restrict__ pos,
      const float* __restrict__ Wt00, const float* __restrict__ Wt11,
      const float* __restrict__ Wmono, const float* __restrict__ ebias,
      float* __restrict__ out) {
    int lane = threadIdx.x & 31;
    int n = (blockIdx.x * blockDim.x + threadIdx.x) >> 5;
    if (n >= NN) return;
    const float* gx = (const float*)g_x4;
    const size_t nb = (size_t)n * (FF * NPAD) + lane * NPAD;

    float x0 = gx[nb + 0];
    float tj[4];
    #pragma unroll
    for (int j = 0; j < 4; j++) {
        float p = x0 * Wt00[lane * 4 + j];
        #pragma unroll
        for (int o = 16; o > 0; o >>= 1) p += __shfl_xor_sync(0xffffffffu, p, o);
        tj[j] = p;
    }
    if (lane < 4) {
        float m = 0.0f;
        #pragma unroll
        for (int k = 0; k < 4; k++) m = fmaf(tj[k], Wmono[k * 4 + lane], m);
        m += ebias[z[n]];
        out[n * 4 + lane] = m;
    }
    #pragma unroll
    for (int c = 0; c < 3; c++) {
        float xc = gx[nb + 1 + c];
        #pragma unroll
        for (int j = 0; j < 4; j++) {
            float p = xc * Wt11[lane * 4 + j];
            #pragma unroll
            for (int o = 16; o > 0; o >>= 1) p += __shfl_xor_sync(0xffffffffu, p, o);
            if (lane == 0) {
                float sv = p / (1.0f + expf(-p));
                sv = fminf(fmaxf(sv, -0.3f), 0.3f);
                out[NN * 4 + (n * 3 + c) * 4 + j] = sv + pos[n * 3 + c];
            }
        }
    }
}

// ---------------- launch --------------------------------------------------
extern "C" void kernel_launch(void* const* d_in, const int* in_sizes, int n_in,
                              void* d_out, int out_size) {
    const int*   z     = (const int*)d_in[0];
    const float* pos   = (const float*)d_in[1];
    const int*   dst   = (const int*)d_in[2];
    const int*   src   = (const int*)d_in[3];
    const float* embed = (const float*)d_in[4];
    const float* Wb    = (const float*)d_in[5];
    const float* W1    = (const float*)d_in[6];
    const float* b1    = (const float*)d_in[7];
    const float* W2    = (const float*)d_in[8];
    const float* b2    = (const float*)d_in[9];
    const float* Wt00  = (const float*)d_in[10];
    const float* Wt11  = (const float*)d_in[11];
    const float* Wmono = (const float*)d_in[12];
    const float* ebias = (const float*)d_in[13];
    float* out = (float*)d_out;

    k_init<<<(NN * NODE_F4 + 255) / 256, 256>>>(z, embed);
    k_geom<<<(EE + 255) / 256, 256>>>(pos, dst, src);   // + dst histogram
    k_scan<<<1, 1024>>>();
    k_scat<<<(EE + 255) / 256, 256>>>(dst, src);
    for (int i = 0; i < 3; i++) {
        k_edge<<<1250, 256>>>(Wb + i * 3 * 16 * 32);
        k_node<<<(NN * 32 + 255) / 256, 256>>>(W1 + i * 3 * 32 * 32, b1 + i * 32,
                                               W2 + i * 3 * 32 * 32, b2 + i * 32);
    }
    k_out<<<(NN * 32 + 255) / 256, 256>>>(z, pos, Wt00, Wt11, Wmono, ebias, out);
}

// round 17
// speedup vs baseline: 1.0977x; 1.0977x over previous
#include <cuda_runtime.h>
#include <math.h>

#define NN 10000
#define EE 160000
#define FF 32
#define NCH 9
#define NPAD 12                 // padded channel dim (16B-aligned lane chunks)
#define NODE_F4 (FF * NPAD / 4) // 96 float4 per node

// ---------------- device scratch (static, no allocations) ----------------
__device__ float4 g_xa[NN * NODE_F4];    // x ping  [node][feature][ch(12)]
__device__ float4 g_xb[NN * NODE_F4];    // x pong
__device__ float  g_geo[EE * 25];        // per CSR slot: sph[9], rad[16]
__device__ int    g_cnt[NN];             // histogram / scatter cursor
__device__ int    g_off[NN + 1];         // CSR offsets
__device__ int    g_csr_src[EE];         // src node per CSR slot

// ---------------- compile-time Gaunt coefficients -------------------------
constexpr double dfc(int n) { double v = 1.0; for (int k = n; k >= 2; k -= 2) v *= (double)k; return v; }
constexpr double sphint(int p, int q, int r) {
    return ((p | q | r) & 1) ? 0.0
         : 12.566370614359172464 * dfc(p - 1) * dfc(q - 1) * dfc(r - 1) / dfc(p + q + r + 1);
}
struct CGTable { float v[9][9][9]; };
constexpr CGTable make_cg() {
    const double TCV[9][2] = {
        {0.28209479177387814, 0.0}, {0.4886025119029199, 0.0}, {0.4886025119029199, 0.0},
        {0.4886025119029199, 0.0}, {1.0925484305920792, 0.0}, {1.0925484305920792, 0.0},
        {3.0 * 0.31539156525252005, -0.31539156525252005}, {1.0925484305920792, 0.0},
        {0.5462742152960396, -0.5462742152960396}};
    const int NTV[9] = {1, 1, 1, 1, 1, 1, 2, 1, 2};
    const int TEV[9][2][3] = {
        {{0,0,0},{0,0,0}}, {{0,1,0},{0,0,0}}, {{0,0,1},{0,0,0}}, {{1,0,0},{0,0,0}},
        {{1,1,0},{0,0,0}}, {{0,1,1},{0,0,0}}, {{0,0,2},{0,0,0}}, {{1,0,1},{0,0,0}},
        {{2,0,0},{0,2,0}}};
    CGTable t{};
    for (int a = 0; a < 9; a++)
      for (int b = 0; b < 9; b++)
        for (int c = 0; c < 9; c++) {
            double g = 0.0;
            for (int i = 0; i < NTV[a]; i++)
              for (int j = 0; j < NTV[b]; j++)
                for (int k = 0; k < NTV[c]; k++)
                    g += TCV[a][i] * TCV[b][j] * TCV[c][k] *
                         sphint(TEV[a][i][0] + TEV[b][j][0] + TEV[c][k][0],
                                TEV[a][i][1] + TEV[b][j][1] + TEV[c][k][1],
                                TEV[a][i][2] + TEV[b][j][2] + TEV[c][k][2]);
            if (g < 1e-6 && g > -1e-6) g = 0.0;
            t.v[a][b][c] = (float)g;
        }
    return t;
}
constexpr CGTable CG_TAB = make_cg();

// ---------------- kernels -------------------------------------------------

__global__ void k_init(const int* __restrict__ z, const float* __restrict__ embed) {
    int idx = blockIdx.x * blockDim.x + threadIdx.x;      // float4 index
    if (idx >= NN * NODE_F4) return;
    if (idx < NN) g_cnt[idx] = 0;
    int r = idx % NODE_F4;
    int n = idx / NODE_F4;
    int f = r / 3, part = r % 3;
    float v0 = (part == 0) ? embed[z[n] * FF + f] : 0.0f;
    g_xa[idx] = make_float4(v0, 0.f, 0.f, 0.f);
}

__global__ void k_hist(const int* __restrict__ dst) {
    int e = blockIdx.x * blockDim.x + threadIdx.x;
    if (e < EE) atomicAdd(&g_cnt[dst[e]], 1);
}

__global__ void __launch_bounds__(1024) k_scan() {
    __shared__ int wsum[32];
    const int t = threadIdx.x;
    const int lane = t & 31, wid = t >> 5;
    const int chunk = (NN + 1023) / 1024;           // 10
    const int beg = t * chunk;
    const int end = (beg + chunk < NN) ? beg + chunk : NN;
    int sum = 0;
    for (int i = beg; i < end; i++) sum += g_cnt[i];
    int v = sum;
    #pragma unroll
    for (int off = 1; off < 32; off <<= 1) {
        int u = __shfl_up_sync(0xffffffffu, v, off);
        if (lane >= off) v += u;
    }
    if (lane == 31) wsum[wid] = v;
    __syncthreads();
    if (wid == 0) {
        int w = wsum[lane];
        #pragma unroll
        for (int off = 1; off < 32; off <<= 1) {
            int u = __shfl_up_sync(0xffffffffu, w, off);
            if (lane >= off) w += u;
        }
        wsum[lane] = w;
    }
    __syncthreads();
    int base = ((wid > 0) ? wsum[wid - 1] : 0) + (v - sum);   // exclusive prefix
    int run = base;
    for (int i = beg; i < end; i++) {
        int c = g_cnt[i];
        g_off[i] = run;
        run += c;
        g_cnt[i] = 0;                               // reset: reused as cursor
    }
    if (t == 1023) g_off[NN] = EE;
}

// geometry computed per edge, written directly into its CSR slot.
__global__ void k_geom_scat(const float* __restrict__ pos, const int* __restrict__ dst,
                            const int* __restrict__ src) {
    int e = blockIdx.x * blockDim.x + threadIdx.x;
    if (e >= EE) return;
    int s = src[e], d = dst[e];
    int slot = g_off[d] + atomicAdd(&g_cnt[d], 1);
    g_csr_src[slot] = s;

    float dx = pos[s * 3 + 0] - pos[d * 3 + 0];
    float dy = pos[s * 3 + 1] - pos[d * 3 + 1];
    float dz = pos[s * 3 + 2] - pos[d * 3 + 2];
    float r = sqrtf(dx * dx + dy * dy + dz * dz + 1e-12f);
    float inv = 1.0f / r;
    float x = dx * inv, y = dy * inv, z = dz * inv;
    const float c0 = 0.28209479177387814f, c1 = 0.4886025119029199f,
                c2a = 1.0925484305920792f, c2b = 0.31539156525252005f,
                c2c = 0.5462742152960396f;
    float* g = &g_geo[(size_t)slot * 25];
    g[0] = c0;
    g[1] = c1 * y;  g[2] = c1 * z;  g[3] = c1 * x;
    g[4] = c2a * x * y; g[5] = c2a * y * z;
    g[6] = c2b * (3.0f * z * z - 1.0f);
    g[7] = c2a * x * z; g[8] = c2c * (x * x - y * y);

    float u1 = 1.0f / (1.0f + r);
    float om = 1.0f - u1;
    float A[16], B[16];
    A[0] = 1.0f;
    #pragma unroll
    for (int k = 1; k < 16; k++) A[k] = A[k - 1] * u1;
    B[15] = 1.0f;
    #pragma unroll
    for (int k = 14; k >= 0; k--) B[k] = B[k + 1] * om;
    float t = r * 0.25f;
    float fc = 0.0f;
    if (t < 1.0f) {
        float den = 1.0f - t * t;
        fc = expf(-t * t / den);
    }
    const float binom[16] = {1.f,15.f,105.f,455.f,1365.f,3003.f,5005.f,6435.f,
                             6435.f,5005.f,3003.f,1365.f,455.f,105.f,15.f,1.f};
    #pragma unroll
    for (int k = 0; k < 16; k++) g[9 + k] = binom[k] * A[k] * B[k] * fc;
}

// fused kernel: warp per dst node. Edge phase (CSR gather, register acc,
// sequential geo) then node phase (dense layers via shfl-matmul) into the
// OTHER x buffer. No g_y, no separate node kernel, no atomics.
__global__ void __launch_bounds__(256, 2)
k_fused(const float* __restrict__ Wb_i,
        const float* __restrict__ W1, const float* __restrict__ b1,
        const float* __restrict__ W2, const float* __restrict__ b2,
        int par) {
    __shared__ float sW1[3 * 32 * 32], sW2[3 * 32 * 32], sb1[32], sb2[32];
    const int t = threadIdx.x;
    for (int i = t; i < 3072; i += 256) { sW1[i] = W1[i]; sW2[i] = W2[i]; }
    if (t < 32) { sb1[t] = b1[t]; sb2[t] = b2[t]; }
    __syncthreads();

    const int lane = t & 31;
    const int warp = (blockIdx.x * blockDim.x + t) >> 5;
    const int nwarp = (gridDim.x * blockDim.x) >> 5;
    const int lsel = (lane < 25 ? lane : 0);

    const float* gx  = (const float*)(par ? g_xb : g_xa);
    float*       gxo = (float*)(par ? g_xa : g_xb);

    float w0[16], w1[16], w2[16];
    #pragma unroll
    for (int n = 0; n < 16; n++) {
        w0[n] = Wb_i[(0 * 16 + n) * 32 + lane];
        w1[n] = Wb_i[(1 * 16 + n) * 32 + lane];
        w2[n] = Wb_i[(2 * 16 + n) * 32 + lane];
    }

    for (int n = warp; n < NN; n += nwarp) {
        const int beg = g_off[n], end = g_off[n + 1];

        float acc[9];
        #pragma unroll
        for (int c = 0; c < 9; c++) acc[c] = 0.f;

        int s = 0; float gv = 0.0f;
        if (beg < end) {
            s = g_csr_src[beg];
            gv = g_geo[(size_t)beg * 25 + lsel];
        }
        for (int i = beg; i < end; i++) {
            // gather x[src] early
            const float4* xp4 = (const float4*)(gx + (size_t)s * (FF * NPAD) + lane * NPAD);
            float4 xv0 = xp4[0];
            float4 xv1 = xp4[1];
            float  xa8 = ((const float*)xp4)[8];

            // prefetch next edge idx/geo (geo now sequential in CSR order)
            int s2 = 0; float gv2 = 0.0f;
            if (i + 1 < end) {
                s2 = g_csr_src[i + 1];
                gv2 = g_geo[(size_t)(i + 1) * 25 + lsel];
            }

            float R0 = 0.f, R1 = 0.f, R2 = 0.f;
            #pragma unroll
            for (int k = 0; k < 16; k++) {
                float rn = __shfl_sync(0xffffffffu, gv, 9 + k);
                R0 = fmaf(rn, w0[k], R0);
                R1 = fmaf(rn, w1[k], R1);
                R2 = fmaf(rn, w2[k], R2);
            }
            float bfv[9];
            #pragma unroll
            for (int b = 0; b < 9; b++) {
                float sb = __shfl_sync(0xffffffffu, gv, b);
                bfv[b] = sb * (b == 0 ? R0 : (b < 4 ? R1 : R2));
            }
            float xa[9] = {xv0.x, xv0.y, xv0.z, xv0.w, xv1.x, xv1.y, xv1.z, xv1.w, xa8};

            float p[9];
            #pragma unroll
            for (int a = 0; a < 9; a++) p[a] = xa[a] * bfv[a];
#define ACCP(A,C) { constexpr float G_ = CG_TAB.v[A][A][C]; if (G_ != 0.0f) acc[C] = fmaf(p[A], G_, acc[C]); }
#define CROSS(A,B) float s##A##B = fmaf(xa[A], bfv[B], xa[B] * bfv[A]);
#define ACCS(A,B,C) { constexpr float G_ = CG_TAB.v[A][B][C]; if (G_ != 0.0f) acc[C] = fmaf(s##A##B, G_, acc[C]); }
            ACCP(0,0) ACCP(0,6) ACCP(0,8)
            ACCP(1,0) ACCP(1,6) ACCP(1,8)
            ACCP(2,0) ACCP(2,6) ACCP(2,8)
            ACCP(3,0) ACCP(3,6) ACCP(3,8)
            ACCP(4,0) ACCP(4,6) ACCP(4,8)
            ACCP(5,0) ACCP(5,6) ACCP(5,8)
            ACCP(6,0) ACCP(6,6) ACCP(6,8)
            ACCP(7,0) ACCP(7,6) ACCP(7,8)
            ACCP(8,0) ACCP(8,6) ACCP(8,8)

            CROSS(0,6) CROSS(0,8) CROSS(6,8)
            ACCS(0,6,0) ACCS(0,6,6) ACCS(0,6,8)
            ACCS(0,8,0) ACCS(0,8,6) ACCS(0,8,8)
            ACCS(6,8,0) ACCS(6,8,6) ACCS(6,8,8)

            CROSS(0,1) CROSS(6,1) CROSS(8,1) CROSS(3,4) CROSS(2,5)
            ACCS(0,1,1) ACCS(6,1,1) ACCS(8,1,1) ACCS(3,4,1) ACCS(2,5,1)

            CROSS(0,2) CROSS(6,2) CROSS(8,2) CROSS(3,7) CROSS(1,5)
            ACCS(0,2,2) ACCS(6,2,2) ACCS(8,2,2) ACCS(3,7,2) ACCS(1,5,2)

            CROSS(0,3) CROSS(6,3) CROSS(8,3) CROSS(1,4) CROSS(2,7)
            ACCS(0,3,3) ACCS(6,3,3) ACCS(8,3,3) ACCS(1,4,3) ACCS(2,7,3)

            CROSS(0,4) CROSS(6,4) CROSS(8,4) CROSS(1,3) CROSS(5,7)
            ACCS(0,4,4) ACCS(6,4,4) ACCS(8,4,4) ACCS(1,3,4) ACCS(5,7,4)

            CROSS(0,5) CROSS(6,5) CROSS(8,5) CROSS(1,2) CROSS(4,7)
            ACCS(0,5,5) ACCS(6,5,5) ACCS(8,5,5) ACCS(1,2,5) ACCS(4,7,5)

            CROSS(0,7) CROSS(6,7) CROSS(8,7) CROSS(2,3) CROSS(4,5)
            ACCS(0,7,7) ACCS(6,7,7) ACCS(8,7,7) ACCS(2,3,7) ACCS(4,5,7)
#undef ACCP
#undef CROSS
#undef ACCS
            s = s2; gv = gv2;
        }

        // ---- node phase: y = x + acc; h = silu(W1 y + b1); x' = x + W2 h + b2
        const size_t nb = (size_t)n * (FF * NPAD) + lane * NPAD;
        const float4* xi4 = (const float4*)(gx + nb);
        float4 xA = xi4[0], xB = xi4[1], xC = xi4[2];

        const int DEGc[9] = {0, 1, 1, 1, 2, 2, 2, 2, 2};
        float yv[9], h[9], o[9];
        yv[0] = xA.x + acc[0]; yv[1] = xA.y + acc[1]; yv[2] = xA.z + acc[2]; yv[3] = xA.w + acc[3];
        yv[4] = xB.x + acc[4]; yv[5] = xB.y + acc[5]; yv[6] = xB.z + acc[6]; yv[7] = xB.w + acc[7];
        yv[8] = xC.x + acc[8];

        #pragma unroll
        for (int c = 0; c < 9; c++) {
            int d = DEGc[c];
            float a = (c == 0) ? sb1[lane] : 0.0f;
            #pragma unroll
            for (int f = 0; f < 32; f++) {
                float v = __shfl_sync(0xffffffffu, yv[c], f);
                a = fmaf(v, sW1[(d * 32 + f) * 32 + lane], a);
            }
            h[c] = a / (1.0f + __expf(-a));   // silu
        }
        #pragma unroll
        for (int c = 0; c < 9; c++) {
            int d = DEGc[c];
            float a = (c == 0) ? sb2[lane] : 0.0f;
            #pragma unroll
            for (int f = 0; f < 32; f++) {
                float v = __shfl_sync(0xffffffffu, h[c], f);
                a = fmaf(v, sW2[(d * 32 + f) * 32 + lane], a);
            }
            o[c] = a;
        }
        float4* xo4 = (float4*)(gxo + nb);
        xo4[0] = make_float4(xA.x + o[0], xA.y + o[1], xA.z + o[2], xA.w + o[3]);
        xo4[1] = make_float4(xB.x + o[4], xB.y + o[5], xB.z + o[6], xB.w + o[7]);
        xo4[2] = make_float4(xC.x + o[8], 0.f, 0.f, 0.f);
    }
}

// output head: mono (N,4) then dip (N,3,4). Reads g_xb (final after 3 iters).
__global__ void __launch_bounds__(256)
k_out(const int* __restrict__ z, const float* __restrict__ pos,
      const float* __restrict__ Wt00, const float* __restrict__ Wt11,
      const float* __restrict__ Wmono, const float* __restrict__ ebias,
      float* __restrict__ out) {
    int lane = threadIdx.x & 31;
    int n = (blockIdx.x * blockDim.x + threadIdx.x) >> 5;
    if (n >= NN) return;
    const float* gx = (const float*)g_xb;
    const size_t nb = (size_t)n * (FF * NPAD) + lane * NPAD;

    float x0 = gx[nb + 0];
    float tj[4];
    #pragma unroll
    for (int j = 0; j < 4; j++) {
        float p = x0 * Wt00[lane * 4 + j];
        #pragma unroll
        for (int o = 16; o > 0; o >>= 1) p += __shfl_xor_sync(0xffffffffu, p, o);
        tj[j] = p;
    }
    if (lane < 4) {
        float m = 0.0f;
        #pragma unroll
        for (int k = 0; k < 4; k++) m = fmaf(tj[k], Wmono[k * 4 + lane], m);
        m += ebias[z[n]];
        out[n * 4 + lane] = m;
    }
    #pragma unroll
    for (int c = 0; c < 3; c++) {
        float xc = gx[nb + 1 + c];
        #pragma unroll
        for (int j = 0; j < 4; j++) {
            float p = xc * Wt11[lane * 4 + j];
            #pragma unroll
            for (int o = 16; o > 0; o >>= 1) p += __shfl_xor_sync(0xffffffffu, p, o);
            if (lane == 0) {
                float sv = p / (1.0f + expf(-p));
                sv = fminf(fmaxf(sv, -0.3f), 0.3f);
                out[NN * 4 + (n * 3 + c) * 4 + j] = sv + pos[n * 3 + c];
            }
        }
    }
}

// ---------------- launch --------------------------------------------------
extern "C" void kernel_launch(void* const* d_in, const int* in_sizes, int n_in,
                              void* d_out, int out_size) {
    const int*   z     = (const int*)d_in[0];
    const float* pos   = (const float*)d_in[1];
    const int*   dst   = (const int*)d_in[2];
    const int*   src   = (const int*)d_in[3];
    const float* embed = (const float*)d_in[4];
    const float* Wb    = (const float*)d_in[5];
    const float* W1    = (const float*)d_in[6];
    const float* b1    = (const float*)d_in[7];
    const float* W2    = (const float*)d_in[8];
    const float* b2    = (const float*)d_in[9];
    const float* Wt00  = (const float*)d_in[10];
    const float* Wt11  = (const float*)d_in[11];
    const float* Wmono = (const float*)d_in[12];
    const float* ebias = (const float*)d_in[13];
    float* out = (float*)d_out;

    k_init<<<(NN * NODE_F4 + 255) / 256, 256>>>(z, embed);
    k_hist<<<(EE + 255) / 256, 256>>>(dst);
    k_scan<<<1, 1024>>>();
    k_geom_scat<<<(EE + 255) / 256, 256>>>(pos, dst, src);
    for (int i = 0; i < 3; i++) {
        k_fused<<<1250, 256>>>(Wb + i * 3 * 16 * 32,
                               W1 + i * 3 * 32 * 32, b1 + i * 32,
                               W2 + i * 3 * 32 * 32, b2 + i * 32,
                               i & 1);
    }
    k_out<<<(NN * 32 + 255) / 256, 256>>>(z, pos, Wt00, Wt11, Wmono, ebias, out);
}